// round 1
// baseline (speedup 1.0000x reference)
#include <cuda_runtime.h>

#define NN 100000
#define EE 1600000
#define NEG_SLOPE 0.2f

// ---------------- scratch (static device globals; no allocation) ----------------
__device__ int   g_deg[NN];
__device__ int   g_cursor[NN];
__device__ int   g_rowptr[NN];
__device__ int   g_bsum[1024];
__device__ int   g_csr_src[EE];
__device__ float g_ebuf[EE];
__device__ float g_feat[(size_t)NN * 32];
__device__ float g_el[NN];
__device__ float g_er[NN];
__device__ float g_out1[(size_t)NN * 32];

// ---------------- CSR build ----------------
__global__ void k_zero(int N) {
    int i = blockIdx.x * blockDim.x + threadIdx.x;
    if (i < N) { g_deg[i] = 0; g_cursor[i] = 0; }
}

__global__ void k_hist(const int* __restrict__ dst, int E) {
    int i = blockIdx.x * blockDim.x + threadIdx.x;
    if (i < E) atomicAdd(&g_deg[dst[i]], 1);
}

// per-block exclusive scan over 512-elem tiles
__global__ void k_scan_block(int N) {
    __shared__ int sh[512];
    int t = threadIdx.x;
    int i = blockIdx.x * 512 + t;
    int v = (i < N) ? g_deg[i] : 0;
    sh[t] = v;
    __syncthreads();
#pragma unroll
    for (int o = 1; o < 512; o <<= 1) {
        int x = (t >= o) ? sh[t - o] : 0;
        __syncthreads();
        sh[t] += x;
        __syncthreads();
    }
    if (i < N) g_rowptr[i] = sh[t] - v;      // exclusive within block
    if (t == 511) g_bsum[blockIdx.x] = sh[511];
}

// single-block exclusive scan of block sums (nb <= 1024)
__global__ void k_scan_bsum(int nb) {
    __shared__ int sh[1024];
    int t = threadIdx.x;
    int v = (t < nb) ? g_bsum[t] : 0;
    sh[t] = v;
    __syncthreads();
#pragma unroll
    for (int o = 1; o < 1024; o <<= 1) {
        int x = (t >= o) ? sh[t - o] : 0;
        __syncthreads();
        sh[t] += x;
        __syncthreads();
    }
    if (t < nb) g_bsum[t] = sh[t] - v;       // exclusive
}

__global__ void k_scan_add(int N) {
    int i = blockIdx.x * blockDim.x + threadIdx.x;
    if (i < N) g_rowptr[i] += g_bsum[i >> 9];
}

__global__ void k_scatter(const int* __restrict__ src, const int* __restrict__ dst, int E) {
    int i = blockIdx.x * blockDim.x + threadIdx.x;
    if (i < E) {
        int d = dst[i];
        int pos = g_rowptr[d] + atomicAdd(&g_cursor[d], 1);
        g_csr_src[pos] = src[i];
    }
}

// ---------------- GEMM + attention projections ----------------
// feat = h @ W^T  (Dout = 32), el = feat @ al, er = feat @ ar
// One warp per node; W transposed into shared for conflict-free access.
template <int DIN>
__global__ void k_gemm_attn(const float* __restrict__ h_ext,
                            const float* __restrict__ W,
                            const float* __restrict__ al,
                            const float* __restrict__ ar,
                            int use_internal_in, int N) {
    __shared__ float Wt[DIN * 32];      // Wt[k*32 + f]
    __shared__ float sal[32], sar[32];
    __shared__ float hs[8][DIN];

    const float* h = use_internal_in ? g_out1 : h_ext;

    int tid = threadIdx.x;
    for (int i = tid; i < DIN * 32; i += blockDim.x) {
        int f = i / DIN, k = i - f * DIN;
        Wt[k * 32 + f] = W[i];          // W row-major (32, DIN), coalesced read
    }
    if (tid < 32) { sal[tid] = al[tid]; sar[tid] = ar[tid]; }
    __syncthreads();

    int warp = tid >> 5, lane = tid & 31;
    int n = blockIdx.x * 8 + warp;
    if (n >= N) return;

    float* hrow = hs[warp];
    if (DIN == 128) {
        float4 v = ((const float4*)(h + (size_t)n * DIN))[lane];
        ((float4*)hrow)[lane] = v;
    } else {
        hrow[lane] = h[(size_t)n * DIN + lane];
    }
    __syncwarp();

    float acc = 0.f;
#pragma unroll
    for (int k = 0; k < DIN; k++)
        acc += hrow[k] * Wt[k * 32 + lane];

    g_feat[(size_t)n * 32 + lane] = acc;

    float vl = acc * sal[lane];
    float vr = acc * sar[lane];
#pragma unroll
    for (int o = 16; o; o >>= 1) {
        vl += __shfl_xor_sync(0xffffffffu, vl, o);
        vr += __shfl_xor_sync(0xffffffffu, vr, o);
    }
    if (lane == 0) { g_el[n] = vl; g_er[n] = vr; }
}

// ---------------- per-node edge softmax + aggregation ----------------
// one warp per dst node; lane = output feature
__global__ void k_aggregate(const float* __restrict__ b,
                            float* __restrict__ out_ext,
                            int use_internal_out, int N) {
    float* out = use_internal_out ? g_out1 : out_ext;

    int gwarp = (blockIdx.x * blockDim.x + threadIdx.x) >> 5;
    int lane = threadIdx.x & 31;
    if (gwarp >= N) return;
    int n = gwarp;

    int start = g_rowptr[n];
    int cnt   = g_deg[n];
    float bias = b[lane];
    if (cnt == 0) { out[(size_t)n * 32 + lane] = bias; return; }

    float ern = g_er[n];

    // pass 1: compute e (leaky relu), stash, warp max
    float m = -3.4e38f;
    for (int i = lane; i < cnt; i += 32) {
        int s = g_csr_src[start + i];
        float e = g_el[s] + ern;
        e = (e >= 0.f) ? e : NEG_SLOPE * e;
        g_ebuf[start + i] = e;
        m = fmaxf(m, e);
    }
#pragma unroll
    for (int o = 16; o; o >>= 1) m = fmaxf(m, __shfl_xor_sync(0xffffffffu, m, o));
    __syncwarp();   // make g_ebuf writes visible across lanes

    // pass 2: exp-sum
    float ssum = 0.f;
    for (int i = lane; i < cnt; i += 32) ssum += __expf(g_ebuf[start + i] - m);
#pragma unroll
    for (int o = 16; o; o >>= 1) ssum += __shfl_xor_sync(0xffffffffu, ssum, o);
    float inv = 1.f / ssum;

    // pass 3: weighted feature accumulation (serial edges, lane = feature)
    float acc = 0.f;
    int s = g_csr_src[start];           // 1-deep prefetch of gather index
    for (int j = 0; j < cnt; j++) {
        int s_next = (j + 1 < cnt) ? g_csr_src[start + j + 1] : 0;
        float alpha = __expf(g_ebuf[start + j] - m) * inv;
        acc += alpha * g_feat[(size_t)s * 32 + lane];
        s = s_next;
    }
    out[(size_t)n * 32 + lane] = acc + bias;
}

// ---------------- driver ----------------
extern "C" void kernel_launch(void* const* d_in, const int* in_sizes, int n_in,
                              void* d_out, int out_size) {
    const float* features = (const float*)d_in[0];
    const int*   src      = (const int*)d_in[1];
    const int*   dst      = (const int*)d_in[2];
    const float* W1  = (const float*)d_in[3];
    const float* al1 = (const float*)d_in[4];
    const float* ar1 = (const float*)d_in[5];
    const float* b1  = (const float*)d_in[6];
    const float* W2  = (const float*)d_in[7];
    const float* al2 = (const float*)d_in[8];
    const float* ar2 = (const float*)d_in[9];
    const float* b2  = (const float*)d_in[10];

    int E = in_sizes[1];
    int N = in_sizes[0] / 128;
    if (N > NN) N = NN;
    if (E > EE) E = EE;

    float* out = (float*)d_out;

    const int T = 256;
    int gN = (N + T - 1) / T;
    int gE = (E + T - 1) / T;
    int nScanBlocks = (N + 511) / 512;

    // ---- CSR build (shared by both layers) ----
    k_zero<<<gN, T>>>(N);
    k_hist<<<gE, T>>>(dst, E);
    k_scan_block<<<nScanBlocks, 512>>>(N);
    k_scan_bsum<<<1, 1024>>>(nScanBlocks);
    k_scan_add<<<gN, T>>>(N);
    k_scatter<<<gE, T>>>(src, dst, E);

    int gWarp = (N + 7) / 8;   // 8 warps (one node each) per 256-thread block

    // ---- layer 1 ----
    k_gemm_attn<128><<<gWarp, T>>>(features, W1, al1, ar1, /*internal_in=*/0, N);
    k_aggregate<<<gWarp, T>>>(b1, out, /*internal_out=*/1, N);

    // ---- layer 2 ----
    k_gemm_attn<32><<<gWarp, T>>>(nullptr, W2, al2, ar2, /*internal_in=*/1, N);
    k_aggregate<<<gWarp, T>>>(b2, out, /*internal_out=*/0, N);
}

// round 2
// speedup vs baseline: 2.4044x; 2.4044x over previous
#include <cuda_runtime.h>

#define NN 100000
#define EE 1600000
#define NEG_SLOPE 0.2f

// ---------------- scratch (static device globals; no allocation) ----------------
__device__ int   g_deg[NN];
__device__ int   g_cursor[NN];
__device__ int   g_rowptr[NN];
__device__ int   g_bsum[1024];
__device__ int   g_csr_src[EE];
__device__ float g_ebuf[EE];
__device__ float g_feat[(size_t)NN * 32];
__device__ float g_el[NN];
__device__ float g_er[NN];
__device__ float g_out1[(size_t)NN * 32];

// ---------------- CSR build ----------------
__global__ void k_zero(int N) {
    int i = blockIdx.x * blockDim.x + threadIdx.x;
    if (i < N) g_deg[i] = 0;
}

__global__ void k_hist(const int* __restrict__ dst, int E) {
    int i = blockIdx.x * blockDim.x + threadIdx.x;
    if (i < E) atomicAdd(&g_deg[dst[i]], 1);
}

// per-block exclusive scan over 512-elem tiles
__global__ void k_scan_block(int N) {
    __shared__ int sh[512];
    int t = threadIdx.x;
    int i = blockIdx.x * 512 + t;
    int v = (i < N) ? g_deg[i] : 0;
    sh[t] = v;
    __syncthreads();
#pragma unroll
    for (int o = 1; o < 512; o <<= 1) {
        int x = (t >= o) ? sh[t - o] : 0;
        __syncthreads();
        sh[t] += x;
        __syncthreads();
    }
    if (i < N) g_rowptr[i] = sh[t] - v;      // exclusive within block
    if (t == 511) g_bsum[blockIdx.x] = sh[511];
}

// single-block exclusive scan of block sums (nb <= 1024)
__global__ void k_scan_bsum(int nb) {
    __shared__ int sh[1024];
    int t = threadIdx.x;
    int v = (t < nb) ? g_bsum[t] : 0;
    sh[t] = v;
    __syncthreads();
#pragma unroll
    for (int o = 1; o < 1024; o <<= 1) {
        int x = (t >= o) ? sh[t - o] : 0;
        __syncthreads();
        sh[t] += x;
        __syncthreads();
    }
    if (t < nb) g_bsum[t] = sh[t] - v;       // exclusive
}

__global__ void k_scan_add(int N) {
    int i = blockIdx.x * blockDim.x + threadIdx.x;
    if (i < N) {
        int r = g_rowptr[i] + g_bsum[i >> 9];
        g_rowptr[i] = r;
        g_cursor[i] = r;                     // cursor starts at rowptr
    }
}

__global__ void k_scatter(const int* __restrict__ src, const int* __restrict__ dst, int E) {
    int i = blockIdx.x * blockDim.x + threadIdx.x;
    if (i < E) {
        int pos = atomicAdd(&g_cursor[dst[i]], 1);
        g_csr_src[pos] = src[i];
    }
}

// ---------------- GEMM + attention projections ----------------
// feat = h @ W^T (Dout=32), el = feat@al, er = feat@ar.
// Warp computes 4 nodes (register-blocked), lane = output feature.
// W staged in shared as float4 quads: Wt4[q*32+f] = W[f][4q..4q+3].
template <int DIN>
__global__ void __launch_bounds__(256) k_gemm_attn(
        const float* __restrict__ h_ext,
        const float* __restrict__ W,
        const float* __restrict__ al,
        const float* __restrict__ ar,
        int use_internal_in, int N) {
    constexpr int Q = DIN / 4;
    __shared__ float4 Wt4[Q * 32];
    __shared__ float4 hs4[8][4 * Q];     // [warp][node*Q + q]
    __shared__ float sal[32], sar[32];

    const float* h = use_internal_in ? g_out1 : h_ext;

    int tid = threadIdx.x;
    for (int i = tid; i < Q * 32; i += 256) {
        int f = i / Q, q = i - f * Q;
        Wt4[q * 32 + f] = ((const float4*)W)[i];   // coalesced read of W row-major
    }
    if (tid < 32) { sal[tid] = al[tid]; sar[tid] = ar[tid]; }
    __syncthreads();

    int warp = tid >> 5, lane = tid & 31;
    int nbase = blockIdx.x * 32 + warp * 4;
    float4* hw = hs4[warp];

#pragma unroll
    for (int j = 0; j < 4; j++) {
        int n = nbase + j;
        if (n < N) {
            if (DIN == 128) {
                hw[j * Q + lane] = ((const float4*)(h + (size_t)n * DIN))[lane];
            } else {
                if (lane < Q)
                    hw[j * Q + lane] = ((const float4*)(h + (size_t)n * DIN))[lane];
            }
        }
    }
    __syncwarp();

    float acc[4] = {0.f, 0.f, 0.f, 0.f};
#pragma unroll 4
    for (int q = 0; q < Q; q++) {
        float4 w4 = Wt4[q * 32 + lane];
#pragma unroll
        for (int j = 0; j < 4; j++) {
            float4 h4 = hw[j * Q + q];
            acc[j] = fmaf(w4.x, h4.x, acc[j]);
            acc[j] = fmaf(w4.y, h4.y, acc[j]);
            acc[j] = fmaf(w4.z, h4.z, acc[j]);
            acc[j] = fmaf(w4.w, h4.w, acc[j]);
        }
    }

#pragma unroll
    for (int j = 0; j < 4; j++) {
        int n = nbase + j;
        if (n >= N) break;
        g_feat[(size_t)n * 32 + lane] = acc[j];
        float vl = acc[j] * sal[lane];
        float vr = acc[j] * sar[lane];
#pragma unroll
        for (int o = 16; o; o >>= 1) {
            vl += __shfl_xor_sync(0xffffffffu, vl, o);
            vr += __shfl_xor_sync(0xffffffffu, vr, o);
        }
        if (lane == 0) { g_el[n] = vl; g_er[n] = vr; }
    }
}

// ---------------- per-node edge softmax + aggregation ----------------
// One warp per dst node. Warp shaped as 4 edge-groups x 8 feature-lanes:
// g = lane>>3 handles edge j0+g, r = lane&7 handles features 4r..4r+3.
__global__ void __launch_bounds__(256) k_aggregate(
        const float* __restrict__ b,
        float* __restrict__ out_ext,
        int use_internal_out, int N) {
    float* out = use_internal_out ? g_out1 : out_ext;

    int gwarp = (blockIdx.x * blockDim.x + threadIdx.x) >> 5;
    if (gwarp >= N) return;
    int lane = threadIdx.x & 31;
    int g = lane >> 3, r = lane & 7;
    int n = gwarp;

    int start = g_rowptr[n];
    int cnt   = g_deg[n];
    float4 bias4 = ((const float4*)b)[r];
    float4* out4 = (float4*)out;

    if (cnt == 0) {
        if (g == 0) out4[(size_t)n * 8 + r] = bias4;
        return;
    }

    float ern = g_er[n];

    // pass 1: e = leaky_relu(el[src]+er[n]); stash + warp max
    float m = -3.4e38f;
    for (int i = lane; i < cnt; i += 32) {
        int s = g_csr_src[start + i];
        float e = g_el[s] + ern;
        e = (e >= 0.f) ? e : NEG_SLOPE * e;
        g_ebuf[start + i] = e;
        m = fmaxf(m, e);
    }
#pragma unroll
    for (int o = 16; o; o >>= 1) m = fmaxf(m, __shfl_xor_sync(0xffffffffu, m, o));
    __syncwarp();

    // pass 2: exp-sum
    float ssum = 0.f;
    for (int i = lane; i < cnt; i += 32) ssum += __expf(g_ebuf[start + i] - m);
#pragma unroll
    for (int o = 16; o; o >>= 1) ssum += __shfl_xor_sync(0xffffffffu, ssum, o);
    float inv = 1.f / ssum;

    // pass 3: 4 edges per iteration, coalesced float4 feature gathers
    float4 acc = {0.f, 0.f, 0.f, 0.f};
    const float4* feat4 = (const float4*)g_feat;
    for (int j0 = 0; j0 < cnt; j0 += 4) {
        int j = j0 + g;
        float alpha = 0.f;
        int s = 0;
        if (j < cnt) {
            s = g_csr_src[start + j];
            alpha = __expf(g_ebuf[start + j] - m) * inv;
        }
        float4 f4 = feat4[(size_t)s * 8 + r];
        acc.x = fmaf(alpha, f4.x, acc.x);
        acc.y = fmaf(alpha, f4.y, acc.y);
        acc.z = fmaf(alpha, f4.z, acc.z);
        acc.w = fmaf(alpha, f4.w, acc.w);
    }
    // reduce across the 4 edge-groups
#pragma unroll
    for (int o = 8; o <= 16; o <<= 1) {
        acc.x += __shfl_xor_sync(0xffffffffu, acc.x, o);
        acc.y += __shfl_xor_sync(0xffffffffu, acc.y, o);
        acc.z += __shfl_xor_sync(0xffffffffu, acc.z, o);
        acc.w += __shfl_xor_sync(0xffffffffu, acc.w, o);
    }
    if (g == 0) {
        acc.x += bias4.x; acc.y += bias4.y; acc.z += bias4.z; acc.w += bias4.w;
        out4[(size_t)n * 8 + r] = acc;
    }
}

// ---------------- driver ----------------
extern "C" void kernel_launch(void* const* d_in, const int* in_sizes, int n_in,
                              void* d_out, int out_size) {
    const float* features = (const float*)d_in[0];
    const int*   src      = (const int*)d_in[1];
    const int*   dst      = (const int*)d_in[2];
    const float* W1  = (const float*)d_in[3];
    const float* al1 = (const float*)d_in[4];
    const float* ar1 = (const float*)d_in[5];
    const float* b1  = (const float*)d_in[6];
    const float* W2  = (const float*)d_in[7];
    const float* al2 = (const float*)d_in[8];
    const float* ar2 = (const float*)d_in[9];
    const float* b2  = (const float*)d_in[10];

    int E = in_sizes[1];
    int N = in_sizes[0] / 128;
    if (N > NN) N = NN;
    if (E > EE) E = EE;

    float* out = (float*)d_out;

    const int T = 256;
    int gN = (N + T - 1) / T;
    int gE = (E + T - 1) / T;
    int nScanBlocks = (N + 511) / 512;

    // ---- CSR build (shared by both layers) ----
    k_zero<<<gN, T>>>(N);
    k_hist<<<gE, T>>>(dst, E);
    k_scan_block<<<nScanBlocks, 512>>>(N);
    k_scan_bsum<<<1, 1024>>>(nScanBlocks);
    k_scan_add<<<gN, T>>>(N);
    k_scatter<<<gE, T>>>(src, dst, E);

    int gGemm = (N + 31) / 32;   // 8 warps x 4 nodes per 256-thread block
    int gWarp = (N + 7) / 8;     // 8 warps (one node each) per 256-thread block

    // ---- layer 1 ----
    k_gemm_attn<128><<<gGemm, T>>>(features, W1, al1, ar1, /*internal_in=*/0, N);
    k_aggregate<<<gWarp, T>>>(b1, out, /*internal_out=*/1, N);

    // ---- layer 2 ----
    k_gemm_attn<32><<<gGemm, T>>>(nullptr, W2, al2, ar2, /*internal_in=*/1, N);
    k_aggregate<<<gWarp, T>>>(b2, out, /*internal_out=*/0, N);
}